// round 2
// baseline (speedup 1.0000x reference)
#include <cuda_runtime.h>
#include <cstddef>

// Problem constants: B=4, H=16, S=2048, D=64, fp32.
// reference: score = QK^T / sqrt(64); attn = relu(score); ctx = attn @ V
// Output tuple flattened: [context (B*H*S*D)] then [attn (B*H*S*S)].

#define S_LEN 2048
#define HDIM 64
#define NBH 64           // B*H
#define BLK 128          // q-tile and k-tile size
#define NTHREADS 256

#define VS_PAD 68        // V smem row stride (floats)
#define CTX_ELEMS (8388608LL)   // 64*2048*64

// dynamic smem layout (floats):
//  Qs: 128*64 (swizzled)     8192
//  Ks: 128*64 (swizzled)     8192
//  Vs: 128*68                8704
//  Ps: 128*128              16384
#define SMEM_FLOATS (8192 + 8192 + 8704 + 16384)
#define SMEM_BYTES  (SMEM_FLOATS * 4)

// swizzled float4 index for a [128 x 64] tile:
// logical (row, kk4) -> row*16 + (kk4 ^ ((row>>3)&7))
__device__ __forceinline__ int swz_idx(int row, int kk4) {
    return row * 16 + (kk4 ^ ((row >> 3) & 7));
}

__global__ __launch_bounds__(NTHREADS, 1)
void relu_attn_fused_kernel(const float* __restrict__ Q,
                            const float* __restrict__ K,
                            const float* __restrict__ V,
                            float* __restrict__ ctx,
                            float* __restrict__ attn) {
    extern __shared__ float sm[];
    float* Qs = sm;                       // swizzled [128][64]
    float* Ks = Qs + BLK * HDIM;          // swizzled [128][64]
    float* Vs = Ks + BLK * HDIM;          // [128][VS_PAD]
    float* Ps = Vs + BLK * VS_PAD;        // [128][128]

    const int tid = threadIdx.x;
    const int tx  = tid & 15;             // 0..15
    const int ty  = tid >> 4;             // 0..15
    const int bh  = blockIdx.y;
    const int q0  = blockIdx.x * BLK;

    const float* Qg = Q + ((size_t)bh * S_LEN + q0) * HDIM;
    const float* Kg = K + (size_t)bh * S_LEN * HDIM;
    const float* Vg = V + (size_t)bh * S_LEN * HDIM;
    float* attng = attn + ((size_t)bh * S_LEN + q0) * S_LEN;
    float* ctxg  = ctx  + ((size_t)bh * S_LEN + q0) * HDIM;

    // ---- load Q tile into swizzled smem (8 float4 per thread) ----
    {
        const float4* Qg4 = (const float4*)Qg;
        float4* Qs4 = (float4*)Qs;
        #pragma unroll
        for (int it = 0; it < (BLK * HDIM / 4) / NTHREADS; it++) {
            int i = tid + it * NTHREADS;
            int row = i >> 4;        // 16 float4 per 64-float row
            int kk4 = i & 15;
            Qs4[swz_idx(row, kk4)] = Qg4[i];
        }
    }

    const int i0 = ty * 8;   // this thread's 8 q-rows
    const int j0 = tx * 8;   // this thread's 8 k-cols (gemm1)
    const int d0 = tx * 4;   // this thread's 4 d-cols (gemm2)

    float acc2[8][4];
    #pragma unroll
    for (int r = 0; r < 8; r++)
        #pragma unroll
        for (int c = 0; c < 4; c++)
            acc2[r][c] = 0.0f;

    for (int kt = 0; kt < S_LEN / BLK; kt++) {
        __syncthreads();   // previous iteration's gemm2 done before overwriting tiles

        // ---- load K tile (swizzled) and V tile (row-major, padded) ----
        {
            const float4* Kt4 = (const float4*)(Kg + (size_t)kt * BLK * HDIM);
            const float4* Vt4 = (const float4*)(Vg + (size_t)kt * BLK * HDIM);
            float4* Ks4 = (float4*)Ks;
            #pragma unroll
            for (int it = 0; it < (BLK * HDIM / 4) / NTHREADS; it++) {
                int i = tid + it * NTHREADS;
                int row = i >> 4;
                int kk4 = i & 15;
                Ks4[swz_idx(row, kk4)] = Kt4[i];
                *(float4*)&Vs[row * VS_PAD + (kk4 << 2)] = Vt4[i];
            }
        }
        __syncthreads();

        // ---- gemm1: acc[r][c] = sum_d Q[i0+r][d] * K[j0+c][d] ----
        float acc[8][8];
        #pragma unroll
        for (int r = 0; r < 8; r++)
            #pragma unroll
            for (int c = 0; c < 8; c++)
                acc[r][c] = 0.0f;

        const float4* Qs4 = (const float4*)Qs;
        const float4* Ks4 = (const float4*)Ks;
        #pragma unroll 2
        for (int kk4 = 0; kk4 < 16; kk4++) {
            float4 a4[8], b4[8];
            #pragma unroll
            for (int r = 0; r < 8; r++)
                a4[r] = Qs4[swz_idx(i0 + r, kk4)];
            #pragma unroll
            for (int c = 0; c < 8; c++)
                b4[c] = Ks4[swz_idx(j0 + c, kk4)];
            #pragma unroll
            for (int r = 0; r < 8; r++)
                #pragma unroll
                for (int c = 0; c < 8; c++) {
                    acc[r][c] += a4[r].x * b4[c].x;
                    acc[r][c] += a4[r].y * b4[c].y;
                    acc[r][c] += a4[r].z * b4[c].z;
                    acc[r][c] += a4[r].w * b4[c].w;
                }
        }

        // ---- relu(score/8): store to global attn AND smem Ps ----
        #pragma unroll
        for (int r = 0; r < 8; r++) {
            float4 p0, p1;
            p0.x = fmaxf(acc[r][0] * 0.125f, 0.0f);
            p0.y = fmaxf(acc[r][1] * 0.125f, 0.0f);
            p0.z = fmaxf(acc[r][2] * 0.125f, 0.0f);
            p0.w = fmaxf(acc[r][3] * 0.125f, 0.0f);
            p1.x = fmaxf(acc[r][4] * 0.125f, 0.0f);
            p1.y = fmaxf(acc[r][5] * 0.125f, 0.0f);
            p1.z = fmaxf(acc[r][6] * 0.125f, 0.0f);
            p1.w = fmaxf(acc[r][7] * 0.125f, 0.0f);
            int row = i0 + r;
            *(float4*)&Ps[row * BLK + j0]     = p0;
            *(float4*)&Ps[row * BLK + j0 + 4] = p1;
            float* ag = attng + (size_t)row * S_LEN + kt * BLK + j0;
            *(float4*)ag       = p0;
            *(float4*)(ag + 4) = p1;
        }
        __syncthreads();

        // ---- gemm2: acc2[r][c] += sum_j Ps[i0+r][j] * Vs[j][d0+c] ----
        #pragma unroll 2
        for (int j = 0; j < BLK; j += 4) {
            float4 a[8];
            float4 b[4];
            #pragma unroll
            for (int r = 0; r < 8; r++)
                a[r] = *(const float4*)&Ps[(i0 + r) * BLK + j];
            #pragma unroll
            for (int u = 0; u < 4; u++)
                b[u] = *(const float4*)&Vs[(j + u) * VS_PAD + d0];
            #pragma unroll
            for (int r = 0; r < 8; r++) {
                acc2[r][0] += a[r].x * b[0].x + a[r].y * b[1].x + a[r].z * b[2].x + a[r].w * b[3].x;
                acc2[r][1] += a[r].x * b[0].y + a[r].y * b[1].y + a[r].z * b[2].y + a[r].w * b[3].y;
                acc2[r][2] += a[r].x * b[0].z + a[r].y * b[1].z + a[r].z * b[2].z + a[r].w * b[3].z;
                acc2[r][3] += a[r].x * b[0].w + a[r].y * b[1].w + a[r].z * b[2].w + a[r].w * b[3].w;
            }
        }
    }

    // ---- write context ----
    #pragma unroll
    for (int r = 0; r < 8; r++) {
        float4 o;
        o.x = acc2[r][0];
        o.y = acc2[r][1];
        o.z = acc2[r][2];
        o.w = acc2[r][3];
        *(float4*)&ctxg[(size_t)(i0 + r) * HDIM + d0] = o;
    }
}

extern "C" void kernel_launch(void* const* d_in, const int* in_sizes, int n_in,
                              void* d_out, int out_size) {
    const float* Q = (const float*)d_in[0];
    const float* K = (const float*)d_in[1];
    const float* V = (const float*)d_in[2];
    float* ctx  = (float*)d_out;
    float* attn = (float*)d_out + CTX_ELEMS;

    cudaFuncSetAttribute(relu_attn_fused_kernel,
                         cudaFuncAttributeMaxDynamicSharedMemorySize, SMEM_BYTES);

    dim3 grid(S_LEN / BLK, NBH);   // (16, 64)
    relu_attn_fused_kernel<<<grid, NTHREADS, SMEM_BYTES>>>(Q, K, V, ctx, attn);
}

// round 4
// speedup vs baseline: 2.5204x; 2.5204x over previous
#include <cuda_runtime.h>
#include <cstdint>
#include <cstddef>

// B=4,H=16,S=2048,D=64 fp32.  out = [ctx (64*2048*64)] ++ [attn (64*2048*2048)]
// score = QK^T/8 ; attn = relu(score) ; ctx = attn @ V
// Implementation: bf16x3 emulated-fp32 via mma.sync.m16n8k16 (base ISA, no tcgen05).
#define S_LEN 2048
#define HDIM  64
#define BLK   128
#define NT    256
#define CTX_ELEMS 8388608LL

// smem: six bf16 [128 x 64] tiles, 16KB each, XOR-swizzled (chunk ^= row&7)
#define OFF_QH 0
#define OFF_QL 16384
#define OFF_KH 32768
#define OFF_KL 49152
#define OFF_VH 65536
#define OFF_VL 81920
#define SMEM_BYTES 98304

__device__ __forceinline__ uint32_t cvta_smem(const void* p) {
    uint32_t a;
    asm("{ .reg .u64 t; cvta.to.shared.u64 t, %1; cvt.u32.u64 %0, t; }" : "=r"(a) : "l"(p));
    return a;
}

__device__ __forceinline__ void ldsm4(uint32_t r[4], uint32_t a) {
    asm volatile("ldmatrix.sync.aligned.m8n8.x4.shared.b16 {%0,%1,%2,%3}, [%4];"
                 : "=r"(r[0]), "=r"(r[1]), "=r"(r[2]), "=r"(r[3]) : "r"(a));
}
__device__ __forceinline__ void ldsm4t(uint32_t r[4], uint32_t a) {
    asm volatile("ldmatrix.sync.aligned.m8n8.x4.trans.shared.b16 {%0,%1,%2,%3}, [%4];"
                 : "=r"(r[0]), "=r"(r[1]), "=r"(r[2]), "=r"(r[3]) : "r"(a));
}
__device__ __forceinline__ void mma16816(float c[4], const uint32_t a[4],
                                         uint32_t b0, uint32_t b1) {
    asm volatile("mma.sync.aligned.m16n8k16.row.col.f32.bf16.bf16.f32 "
                 "{%0,%1,%2,%3}, {%4,%5,%6,%7}, {%8,%9}, {%0,%1,%2,%3};"
                 : "+f"(c[0]), "+f"(c[1]), "+f"(c[2]), "+f"(c[3])
                 : "r"(a[0]), "r"(a[1]), "r"(a[2]), "r"(a[3]), "r"(b0), "r"(b1));
}
// pack two f32 -> bf16x2 (lo -> low half, hi -> high half)
__device__ __forceinline__ uint32_t packbf(float lo, float hi) {
    uint32_t d;
    asm("cvt.rn.bf16x2.f32 %0, %1, %2;" : "=r"(d) : "f"(hi), "f"(lo));
    return d;
}

// split a float4 into bf16 hi/lo packs and store 8B to swizzled tiles
__device__ __forceinline__ void split_store(char* smc, int offH, int offL,
                                            int row, int c4f, float4 v) {
    uint32_t h0 = packbf(v.x, v.y);
    uint32_t h1 = packbf(v.z, v.w);
    float fx = __uint_as_float(h0 << 16), fy = __uint_as_float(h0 & 0xffff0000u);
    float fz = __uint_as_float(h1 << 16), fw = __uint_as_float(h1 & 0xffff0000u);
    uint32_t l0 = packbf(v.x - fx, v.y - fy);
    uint32_t l1 = packbf(v.z - fz, v.w - fw);
    int chunk = c4f >> 1, within = (c4f & 1) * 8;
    int byte = row * 128 + ((chunk ^ (row & 7)) << 4) + within;
    *(uint2*)(smc + offH + byte) = make_uint2(h0, h1);
    *(uint2*)(smc + offL + byte) = make_uint2(l0, l1);
}

__global__ __launch_bounds__(NT, 1)
void relu_attn_mma_kernel(const float* __restrict__ Q,
                          const float* __restrict__ K,
                          const float* __restrict__ V,
                          float* __restrict__ ctx,
                          float* __restrict__ attn) {
    extern __shared__ char smc[];
    const uint32_t sb = cvta_smem(smc);

    const int tid  = threadIdx.x;
    const int lane = tid & 31;
    const int w    = tid >> 5;          // warp 0..7, owns q rows [w*16, w*16+16)
    const int bh   = blockIdx.y;
    const int q0   = blockIdx.x * BLK;

    const float* Kb = K + (size_t)bh * S_LEN * HDIM;
    const float* Vb = V + (size_t)bh * S_LEN * HDIM;
    float* attng = attn + ((size_t)bh * S_LEN + q0) * S_LEN;
    float* ctxg  = ctx  + ((size_t)bh * S_LEN + q0) * HDIM;

    // ---- load Q tile once (split hi/lo bf16, swizzled) ----
    {
        const float4* Qg4 = (const float4*)(Q + ((size_t)bh * S_LEN + q0) * HDIM);
        #pragma unroll
        for (int it = 0; it < 8; it++) {
            int i = tid + it * NT;
            split_store(smc, OFF_QH, OFF_QL, i >> 4, i & 15, Qg4[i]);
        }
    }

    // ldmatrix lane-address components
    const int aRow      = w * 16 + (lane & 15);            // A (Q) rows
    const int aChunkOff = lane >> 4;                       // k8 half
    const int bRowOff   = (lane & 7) + ((lane >> 4) << 3); // B (K) rows
    const int bChunkOff = (lane >> 3) & 1;
    const int vRowOff   = (lane & 7) + (((lane >> 3) & 1) << 3); // V rows (trans)
    const int vChunkOff = lane >> 4;

    float C2[8][4];
    #pragma unroll
    for (int t = 0; t < 8; t++)
        #pragma unroll
        for (int k = 0; k < 4; k++) C2[t][k] = 0.0f;

    for (int kt = 0; kt < S_LEN / BLK; kt++) {
        __syncthreads();   // everyone done reading previous K/V tiles
        {
            const float4* Kg4 = (const float4*)(Kb + (size_t)kt * BLK * HDIM);
            const float4* Vg4 = (const float4*)(Vb + (size_t)kt * BLK * HDIM);
            #pragma unroll
            for (int it = 0; it < 8; it++) {
                int i = tid + it * NT;
                split_store(smc, OFF_KH, OFF_KL, i >> 4, i & 15, Kg4[i]);
            }
            #pragma unroll
            for (int it = 0; it < 8; it++) {
                int i = tid + it * NT;
                split_store(smc, OFF_VH, OFF_VL, i >> 4, i & 15, Vg4[i]);
            }
        }
        __syncthreads();

        // ---- gemm1: C1[16 rows x 128 cols per warp] = Q K^T (bf16x3) ----
        float C1[16][4];
        #pragma unroll
        for (int t = 0; t < 16; t++)
            #pragma unroll
            for (int k = 0; k < 4; k++) C1[t][k] = 0.0f;

        #pragma unroll
        for (int kc = 0; kc < 4; kc++) {
            uint32_t aH[4], aL[4];
            {
                int ch = kc * 2 + aChunkOff;
                uint32_t ad = sb + OFF_QH + aRow * 128 + ((ch ^ (aRow & 7)) << 4);
                ldsm4(aH, ad);
                ldsm4(aL, ad + 16384);
            }
            #pragma unroll
            for (int nt2 = 0; nt2 < 8; nt2++) {
                int brow = nt2 * 16 + bRowOff;
                int bch  = kc * 2 + bChunkOff;
                uint32_t bd = sb + OFF_KH + brow * 128 + ((bch ^ (brow & 7)) << 4);
                uint32_t bHf[4], bLf[4];
                ldsm4(bHf, bd);
                ldsm4(bLf, bd + 16384);
                mma16816(C1[2 * nt2],     aH, bHf[0], bHf[1]);
                mma16816(C1[2 * nt2],     aL, bHf[0], bHf[1]);
                mma16816(C1[2 * nt2],     aH, bLf[0], bLf[1]);
                mma16816(C1[2 * nt2 + 1], aH, bHf[2], bHf[3]);
                mma16816(C1[2 * nt2 + 1], aL, bHf[2], bHf[3]);
                mma16816(C1[2 * nt2 + 1], aH, bLf[2], bLf[3]);
            }
        }

        // ---- epilogue: relu(score/8), store attn, split P hi/lo in-register ----
        uint32_t PH[16][2], PL[16][2];
        {
            float* ag0 = attng + (size_t)(w * 16 + (lane >> 2)) * S_LEN
                       + (size_t)kt * BLK + (lane & 3) * 2;
            float* ag1 = ag0 + 8 * S_LEN;
            #pragma unroll
            for (int t = 0; t < 16; t++) {
                float p0 = fmaxf(C1[t][0] * 0.125f, 0.0f);
                float p1 = fmaxf(C1[t][1] * 0.125f, 0.0f);
                float p2 = fmaxf(C1[t][2] * 0.125f, 0.0f);
                float p3 = fmaxf(C1[t][3] * 0.125f, 0.0f);
                *(float2*)(ag0 + t * 8) = make_float2(p0, p1);
                *(float2*)(ag1 + t * 8) = make_float2(p2, p3);
                uint32_t h01 = packbf(p0, p1);
                uint32_t h23 = packbf(p2, p3);
                float f0 = __uint_as_float(h01 << 16), f1 = __uint_as_float(h01 & 0xffff0000u);
                float f2 = __uint_as_float(h23 << 16), f3 = __uint_as_float(h23 & 0xffff0000u);
                PH[t][0] = h01;
                PH[t][1] = h23;
                PL[t][0] = packbf(p0 - f0, p1 - f1);
                PL[t][1] = packbf(p2 - f2, p3 - f3);
            }
        }

        // ---- gemm2: C2 += P @ V (bf16x3, A from registers, B via ldmatrix.trans) ----
        #pragma unroll
        for (int kc = 0; kc < 8; kc++) {
            uint32_t ah[4] = { PH[2 * kc][0], PH[2 * kc][1],
                               PH[2 * kc + 1][0], PH[2 * kc + 1][1] };
            uint32_t al[4] = { PL[2 * kc][0], PL[2 * kc][1],
                               PL[2 * kc + 1][0], PL[2 * kc + 1][1] };
            int vrow = kc * 16 + vRowOff;
            #pragma unroll
            for (int nt2 = 0; nt2 < 4; nt2++) {
                int vch = nt2 * 2 + vChunkOff;
                uint32_t vd = sb + OFF_VH + vrow * 128 + ((vch ^ (vrow & 7)) << 4);
                uint32_t bHf[4], bLf[4];
                ldsm4t(bHf, vd);
                ldsm4t(bLf, vd + 16384);
                mma16816(C2[2 * nt2],     ah, bHf[0], bHf[1]);
                mma16816(C2[2 * nt2],     al, bHf[0], bHf[1]);
                mma16816(C2[2 * nt2],     ah, bLf[0], bLf[1]);
                mma16816(C2[2 * nt2 + 1], ah, bHf[2], bHf[3]);
                mma16816(C2[2 * nt2 + 1], al, bHf[2], bHf[3]);
                mma16816(C2[2 * nt2 + 1], ah, bLf[2], bLf[3]);
            }
        }
    }

    // ---- write context ----
    {
        float* cg0 = ctxg + (size_t)(w * 16 + (lane >> 2)) * HDIM + (lane & 3) * 2;
        float* cg1 = cg0 + 8 * HDIM;
        #pragma unroll
        for (int t = 0; t < 8; t++) {
            *(float2*)(cg0 + t * 8) = make_float2(C2[t][0], C2[t][1]);
            *(float2*)(cg1 + t * 8) = make_float2(C2[t][2], C2[t][3]);
        }
    }
}

extern "C" void kernel_launch(void* const* d_in, const int* in_sizes, int n_in,
                              void* d_out, int out_size) {
    const float* Q = (const float*)d_in[0];
    const float* K = (const float*)d_in[1];
    const float* V = (const float*)d_in[2];
    float* ctx  = (float*)d_out;
    float* attn = (float*)d_out + CTX_ELEMS;

    cudaFuncSetAttribute(relu_attn_mma_kernel,
                         cudaFuncAttributeMaxDynamicSharedMemorySize, SMEM_BYTES);
    dim3 grid(S_LEN / BLK, 64);   // (16, 64)
    relu_attn_mma_kernel<<<grid, NT, SMEM_BYTES>>>(Q, K, V, ctx, attn);
}

// round 5
// speedup vs baseline: 2.5910x; 1.0280x over previous
#include <cuda_runtime.h>
#include <cstdint>
#include <cstddef>

// B=4,H=16,S=2048,D=64 fp32.  out = [ctx (64*2048*64)] ++ [attn (64*2048*2048)]
// score = QK^T/8 ; attn = relu(score) ; ctx = attn @ V
// bf16x3 emulated-fp32 via mma.sync.m16n8k16.
// Warp grid 4(q) x 2(n): 32 q-rows x 64 n-cols per warp; gemm2 split-k + smem reduce.
#define S_LEN 2048
#define HDIM  64
#define BLK   128
#define NT    256
#define CTX_ELEMS 8388608LL

#define OFF_QH 0
#define OFF_QL 16384
#define OFF_KH 32768
#define OFF_KL 49152
#define OFF_VH 65536
#define OFF_VL 81920
#define SMEM_BYTES 98304
#define RED_STRIDE 72   // floats; reduction buffer overlays Q/K area after main loop

__device__ __forceinline__ uint32_t cvta_smem(const void* p) {
    uint32_t a;
    asm("{ .reg .u64 t; cvta.to.shared.u64 t, %1; cvt.u32.u64 %0, t; }" : "=r"(a) : "l"(p));
    return a;
}
__device__ __forceinline__ void ldsm4(uint32_t r[4], uint32_t a) {
    asm volatile("ldmatrix.sync.aligned.m8n8.x4.shared.b16 {%0,%1,%2,%3}, [%4];"
                 : "=r"(r[0]), "=r"(r[1]), "=r"(r[2]), "=r"(r[3]) : "r"(a));
}
__device__ __forceinline__ void ldsm4t(uint32_t r[4], uint32_t a) {
    asm volatile("ldmatrix.sync.aligned.m8n8.x4.trans.shared.b16 {%0,%1,%2,%3}, [%4];"
                 : "=r"(r[0]), "=r"(r[1]), "=r"(r[2]), "=r"(r[3]) : "r"(a));
}
__device__ __forceinline__ void mma16816(float c[4], const uint32_t a[4],
                                         uint32_t b0, uint32_t b1) {
    asm volatile("mma.sync.aligned.m16n8k16.row.col.f32.bf16.bf16.f32 "
                 "{%0,%1,%2,%3}, {%4,%5,%6,%7}, {%8,%9}, {%0,%1,%2,%3};"
                 : "+f"(c[0]), "+f"(c[1]), "+f"(c[2]), "+f"(c[3])
                 : "r"(a[0]), "r"(a[1]), "r"(a[2]), "r"(a[3]), "r"(b0), "r"(b1));
}
__device__ __forceinline__ uint32_t packbf(float lo, float hi) {
    uint32_t d;
    asm("cvt.rn.bf16x2.f32 %0, %1, %2;" : "=r"(d) : "f"(hi), "f"(lo));
    return d;
}
__device__ __forceinline__ void split_store(char* smc, int offH, int offL,
                                            int row, int c4f, float4 v) {
    uint32_t h0 = packbf(v.x, v.y);
    uint32_t h1 = packbf(v.z, v.w);
    float fx = __uint_as_float(h0 << 16), fy = __uint_as_float(h0 & 0xffff0000u);
    float fz = __uint_as_float(h1 << 16), fw = __uint_as_float(h1 & 0xffff0000u);
    uint32_t l0 = packbf(v.x - fx, v.y - fy);
    uint32_t l1 = packbf(v.z - fz, v.w - fw);
    int chunk = c4f >> 1, within = (c4f & 1) * 8;
    int byte = row * 128 + ((chunk ^ (row & 7)) << 4) + within;
    *(uint2*)(smc + offH + byte) = make_uint2(h0, h1);
    *(uint2*)(smc + offL + byte) = make_uint2(l0, l1);
}

__global__ __launch_bounds__(NT, 1)
void relu_attn_mma2_kernel(const float* __restrict__ Q,
                           const float* __restrict__ K,
                           const float* __restrict__ V,
                           float* __restrict__ ctx,
                           float* __restrict__ attn) {
    extern __shared__ char smc[];
    const uint32_t sb = cvta_smem(smc);

    const int tid  = threadIdx.x;
    const int lane = tid & 31;
    const int w    = tid >> 5;
    const int wq   = w >> 1;        // 0..3: q rows [wq*32, wq*32+32)
    const int wn   = w & 1;         // 0..1: gemm1 cols [wn*64, wn*64+64)
    const int bh   = blockIdx.y;
    const int q0   = blockIdx.x * BLK;

    const float* Kb = K + (size_t)bh * S_LEN * HDIM;
    const float* Vb = V + (size_t)bh * S_LEN * HDIM;
    float* attng = attn + ((size_t)bh * S_LEN + q0) * S_LEN;
    float* ctxg  = ctx  + ((size_t)bh * S_LEN + q0) * HDIM;

    // ---- load Q tile once (split hi/lo bf16, swizzled) ----
    {
        const float4* Qg4 = (const float4*)(Q + ((size_t)bh * S_LEN + q0) * HDIM);
        #pragma unroll
        for (int it = 0; it < 8; it++) {
            int i = tid + it * NT;
            split_store(smc, OFF_QH, OFF_QL, i >> 4, i & 15, Qg4[i]);
        }
    }

    // ldmatrix lane-address components (same mappings as validated R4 kernel)
    const int aRowL     = lane & 15;
    const int aChunkOff = lane >> 4;
    const int bRowOff   = (lane & 7) + ((lane >> 4) << 3);
    const int bChunkOff = (lane >> 3) & 1;
    const int vRowOff   = (lane & 7) + (((lane >> 3) & 1) << 3);
    const int vChunkOff = lane >> 4;

    float C2[2][8][4];
    #pragma unroll
    for (int g = 0; g < 2; g++)
        #pragma unroll
        for (int t = 0; t < 8; t++)
            #pragma unroll
            for (int k = 0; k < 4; k++) C2[g][t][k] = 0.0f;

    for (int kt = 0; kt < S_LEN / BLK; kt++) {
        __syncthreads();
        {
            const float4* Kg4 = (const float4*)(Kb + (size_t)kt * BLK * HDIM);
            const float4* Vg4 = (const float4*)(Vb + (size_t)kt * BLK * HDIM);
            #pragma unroll
            for (int it = 0; it < 8; it++) {
                int i = tid + it * NT;
                split_store(smc, OFF_KH, OFF_KL, i >> 4, i & 15, Kg4[i]);
            }
            #pragma unroll
            for (int it = 0; it < 8; it++) {
                int i = tid + it * NT;
                split_store(smc, OFF_VH, OFF_VL, i >> 4, i & 15, Vg4[i]);
            }
        }
        __syncthreads();

        // ---- gemm1: C1[2 grp][8 nblk][4] = Q K^T over warp's 32 rows x 64 cols ----
        float C1[2][8][4];
        #pragma unroll
        for (int g = 0; g < 2; g++)
            #pragma unroll
            for (int t = 0; t < 8; t++)
                #pragma unroll
                for (int k = 0; k < 4; k++) C1[g][t][k] = 0.0f;

        #pragma unroll
        for (int kc = 0; kc < 4; kc++) {
            uint32_t aH[2][4], aL[2][4];
            #pragma unroll
            for (int g = 0; g < 2; g++) {
                int arow = wq * 32 + g * 16 + aRowL;
                int ch = kc * 2 + aChunkOff;
                uint32_t ad = sb + OFF_QH + arow * 128 + ((ch ^ (arow & 7)) << 4);
                ldsm4(aH[g], ad);
                ldsm4(aL[g], ad + 16384);
            }
            #pragma unroll
            for (int nt2 = 0; nt2 < 4; nt2++) {
                int brow = wn * 64 + nt2 * 16 + bRowOff;
                int bch  = kc * 2 + bChunkOff;
                uint32_t bd = sb + OFF_KH + brow * 128 + ((bch ^ (brow & 7)) << 4);
                uint32_t bHf[4], bLf[4];
                ldsm4(bHf, bd);
                ldsm4(bLf, bd + 16384);
                #pragma unroll
                for (int g = 0; g < 2; g++) {
                    mma16816(C1[g][2 * nt2],     aH[g], bHf[0], bHf[1]);
                    mma16816(C1[g][2 * nt2],     aL[g], bHf[0], bHf[1]);
                    mma16816(C1[g][2 * nt2],     aH[g], bLf[0], bLf[1]);
                    mma16816(C1[g][2 * nt2 + 1], aH[g], bHf[2], bHf[3]);
                    mma16816(C1[g][2 * nt2 + 1], aL[g], bHf[2], bHf[3]);
                    mma16816(C1[g][2 * nt2 + 1], aH[g], bLf[2], bLf[3]);
                }
            }
        }

        // ---- fused epilogue + gemm2, one 16-k-col chunk (nt2) at a time ----
        #pragma unroll
        for (int nt2 = 0; nt2 < 4; nt2++) {
            uint32_t ah[2][4], al[2][4];
            #pragma unroll
            for (int g = 0; g < 2; g++) {
                float* ag = attng
                    + (size_t)(wq * 32 + g * 16 + (lane >> 2)) * S_LEN
                    + (size_t)kt * BLK + wn * 64 + nt2 * 16 + (lane & 3) * 2;
                #pragma unroll
                for (int sub = 0; sub < 2; sub++) {
                    float* c = C1[g][2 * nt2 + sub];
                    float p0 = fmaxf(c[0] * 0.125f, 0.0f);
                    float p1 = fmaxf(c[1] * 0.125f, 0.0f);
                    float p2 = fmaxf(c[2] * 0.125f, 0.0f);
                    float p3 = fmaxf(c[3] * 0.125f, 0.0f);
                    *(float2*)(ag + sub * 8)             = make_float2(p0, p1);
                    *(float2*)(ag + sub * 8 + 8 * S_LEN) = make_float2(p2, p3);
                    uint32_t h01 = packbf(p0, p1);
                    uint32_t h23 = packbf(p2, p3);
                    float f0 = __uint_as_float(h01 << 16), f1 = __uint_as_float(h01 & 0xffff0000u);
                    float f2 = __uint_as_float(h23 << 16), f3 = __uint_as_float(h23 & 0xffff0000u);
                    ah[g][2 * sub]     = h01;
                    ah[g][2 * sub + 1] = h23;
                    al[g][2 * sub]     = packbf(p0 - f0, p1 - f1);
                    al[g][2 * sub + 1] = packbf(p2 - f2, p3 - f3);
                }
            }
            int vrow = wn * 64 + nt2 * 16 + vRowOff;
            #pragma unroll
            for (int ntV = 0; ntV < 4; ntV++) {
                int vch = ntV * 2 + vChunkOff;
                uint32_t vd = sb + OFF_VH + vrow * 128 + ((vch ^ (vrow & 7)) << 4);
                uint32_t bHf[4], bLf[4];
                ldsm4t(bHf, vd);
                ldsm4t(bLf, vd + 16384);
                #pragma unroll
                for (int g = 0; g < 2; g++) {
                    mma16816(C2[g][2 * ntV],     ah[g], bHf[0], bHf[1]);
                    mma16816(C2[g][2 * ntV],     al[g], bHf[0], bHf[1]);
                    mma16816(C2[g][2 * ntV],     ah[g], bLf[0], bLf[1]);
                    mma16816(C2[g][2 * ntV + 1], ah[g], bHf[2], bHf[3]);
                    mma16816(C2[g][2 * ntV + 1], al[g], bHf[2], bHf[3]);
                    mma16816(C2[g][2 * ntV + 1], ah[g], bLf[2], bLf[3]);
                }
            }
        }
    }

    // ---- split-k reduction of C2 across wn pairs, then write ctx ----
    __syncthreads();                 // everyone done with K/V/Q tiles
    float* red = (float*)smc;        // [128 rows][RED_STRIDE] overlays Q/K area
    if (wn == 1) {
        #pragma unroll
        for (int g = 0; g < 2; g++) {
            int r = wq * 32 + g * 16 + (lane >> 2);
            #pragma unroll
            for (int t = 0; t < 8; t++) {
                int col = (t >> 1) * 16 + (t & 1) * 8 + (lane & 3) * 2;
                *(float2*)&red[(size_t)r * RED_STRIDE + col] =
                    make_float2(C2[g][t][0], C2[g][t][1]);
                *(float2*)&red[(size_t)(r + 8) * RED_STRIDE + col] =
                    make_float2(C2[g][t][2], C2[g][t][3]);
            }
        }
    }
    __syncthreads();
    if (wn == 0) {
        #pragma unroll
        for (int g = 0; g < 2; g++) {
            int r = wq * 32 + g * 16 + (lane >> 2);
            #pragma unroll
            for (int t = 0; t < 8; t++) {
                int col = (t >> 1) * 16 + (t & 1) * 8 + (lane & 3) * 2;
                float2 p0 = *(float2*)&red[(size_t)r * RED_STRIDE + col];
                float2 p1 = *(float2*)&red[(size_t)(r + 8) * RED_STRIDE + col];
                *(float2*)&ctxg[(size_t)r * HDIM + col] =
                    make_float2(C2[g][t][0] + p0.x, C2[g][t][1] + p0.y);
                *(float2*)&ctxg[(size_t)(r + 8) * HDIM + col] =
                    make_float2(C2[g][t][2] + p1.x, C2[g][t][3] + p1.y);
            }
        }
    }
}

extern "C" void kernel_launch(void* const* d_in, const int* in_sizes, int n_in,
                              void* d_out, int out_size) {
    const float* Q = (const float*)d_in[0];
    const float* K = (const float*)d_in[1];
    const float* V = (const float*)d_in[2];
    float* ctx  = (float*)d_out;
    float* attn = (float*)d_out + CTX_ELEMS;

    cudaFuncSetAttribute(relu_attn_mma2_kernel,
                         cudaFuncAttributeMaxDynamicSharedMemorySize, SMEM_BYTES);
    dim3 grid(S_LEN / BLK, 64);
    relu_attn_mma2_kernel<<<grid, NT, SMEM_BYTES>>>(Q, K, V, ctx, attn);
}

// round 6
// speedup vs baseline: 2.9386x; 1.1341x over previous
#include <cuda_runtime.h>
#include <cstdint>
#include <cstddef>

// B=4,H=16,S=2048,D=64 fp32.  out = [ctx (64*2048*64)] ++ [attn (64*2048*2048)]
// score = QK^T/8 ; attn = relu(score) ; ctx = attn @ V
// bf16x3 emulated-fp32 via mma.sync.m16n8k16, cp.async-staged K/V pipeline.
#define S_LEN 2048
#define HDIM  64
#define BLK   128
#define NT    256
#define NTILES (S_LEN / BLK)
#define CTX_ELEMS 8388608LL

#define OFF_QH 0
#define OFF_QL 16384
#define OFF_KH 32768
#define OFF_KL 49152
#define OFF_VH 65536
#define OFF_VL 81920
#define STAGE_K 98304          // fp32 K tile staging (32KB)
#define STAGE_V 131072         // fp32 V tile staging (32KB)
#define SMEM_BYTES 163840
#define RED_STRIDE 72

__device__ __forceinline__ uint32_t cvta_smem(const void* p) {
    uint32_t a;
    asm("{ .reg .u64 t; cvta.to.shared.u64 t, %1; cvt.u32.u64 %0, t; }" : "=r"(a) : "l"(p));
    return a;
}
__device__ __forceinline__ void ldsm4(uint32_t r[4], uint32_t a) {
    asm volatile("ldmatrix.sync.aligned.m8n8.x4.shared.b16 {%0,%1,%2,%3}, [%4];"
                 : "=r"(r[0]), "=r"(r[1]), "=r"(r[2]), "=r"(r[3]) : "r"(a));
}
__device__ __forceinline__ void ldsm4t(uint32_t r[4], uint32_t a) {
    asm volatile("ldmatrix.sync.aligned.m8n8.x4.trans.shared.b16 {%0,%1,%2,%3}, [%4];"
                 : "=r"(r[0]), "=r"(r[1]), "=r"(r[2]), "=r"(r[3]) : "r"(a));
}
__device__ __forceinline__ void mma16816(float c[4], const uint32_t a[4],
                                         uint32_t b0, uint32_t b1) {
    asm volatile("mma.sync.aligned.m16n8k16.row.col.f32.bf16.bf16.f32 "
                 "{%0,%1,%2,%3}, {%4,%5,%6,%7}, {%8,%9}, {%0,%1,%2,%3};"
                 : "+f"(c[0]), "+f"(c[1]), "+f"(c[2]), "+f"(c[3])
                 : "r"(a[0]), "r"(a[1]), "r"(a[2]), "r"(a[3]), "r"(b0), "r"(b1));
}
__device__ __forceinline__ uint32_t packbf(float lo, float hi) {
    uint32_t d;
    asm("cvt.rn.bf16x2.f32 %0, %1, %2;" : "=r"(d) : "f"(hi), "f"(lo));
    return d;
}
__device__ __forceinline__ void split_store(char* smc, int offH, int offL,
                                            int row, int c4f, float4 v) {
    uint32_t h0 = packbf(v.x, v.y);
    uint32_t h1 = packbf(v.z, v.w);
    float fx = __uint_as_float(h0 << 16), fy = __uint_as_float(h0 & 0xffff0000u);
    float fz = __uint_as_float(h1 << 16), fw = __uint_as_float(h1 & 0xffff0000u);
    uint32_t l0 = packbf(v.x - fx, v.y - fy);
    uint32_t l1 = packbf(v.z - fz, v.w - fw);
    int chunk = c4f >> 1, within = (c4f & 1) * 8;
    int byte = row * 128 + ((chunk ^ (row & 7)) << 4) + within;
    *(uint2*)(smc + offH + byte) = make_uint2(h0, h1);
    *(uint2*)(smc + offL + byte) = make_uint2(l0, l1);
}
__device__ __forceinline__ void cp16(uint32_t saddr, const void* g) {
    asm volatile("cp.async.cg.shared.global [%0], [%1], 16;" :: "r"(saddr), "l"(g) : "memory");
}
#define CP_COMMIT() asm volatile("cp.async.commit_group;" ::: "memory")
#define CP_WAIT0()  asm volatile("cp.async.wait_group 0;" ::: "memory")

__global__ __launch_bounds__(NT, 1)
void relu_attn_mma3_kernel(const float* __restrict__ Q,
                           const float* __restrict__ K,
                           const float* __restrict__ V,
                           float* __restrict__ ctx,
                           float* __restrict__ attn) {
    extern __shared__ char smc[];
    const uint32_t sb = cvta_smem(smc);

    const int tid  = threadIdx.x;
    const int lane = tid & 31;
    const int w    = tid >> 5;
    const int wq   = w >> 1;        // 0..3: q rows [wq*32, wq*32+32)
    const int wn   = w & 1;         // 0..1: gemm1 cols [wn*64, wn*64+64)
    const int bh   = blockIdx.y;
    const int q0   = blockIdx.x * BLK;

    const float* Kb = K + (size_t)bh * S_LEN * HDIM;
    const float* Vb = V + (size_t)bh * S_LEN * HDIM;
    float* attng = attn + ((size_t)bh * S_LEN + q0) * S_LEN;
    float* ctxg  = ctx  + ((size_t)bh * S_LEN + q0) * HDIM;

    // ---- stage tile 0 (fp32, cp.async) + load/split Q tile ----
    {
        const float4* Kg4 = (const float4*)Kb;
        const float4* Vg4 = (const float4*)Vb;
        #pragma unroll
        for (int it = 0; it < 8; it++) {
            int i = tid + it * NT;
            cp16(sb + STAGE_K + i * 16, Kg4 + i);
            cp16(sb + STAGE_V + i * 16, Vg4 + i);
        }
        CP_COMMIT();
        const float4* Qg4 = (const float4*)(Q + ((size_t)bh * S_LEN + q0) * HDIM);
        #pragma unroll
        for (int it = 0; it < 8; it++) {
            int i = tid + it * NT;
            split_store(smc, OFF_QH, OFF_QL, i >> 4, i & 15, Qg4[i]);
        }
        CP_WAIT0();
    }
    __syncthreads();

    const int aRowL     = lane & 15;
    const int aChunkOff = lane >> 4;
    const int bRowOff   = (lane & 7) + ((lane >> 4) << 3);
    const int bChunkOff = (lane >> 3) & 1;
    const int vRowOff   = (lane & 7) + (((lane >> 3) & 1) << 3);
    const int vChunkOff = lane >> 4;

    float C2[2][8][4];
    #pragma unroll
    for (int g = 0; g < 2; g++)
        #pragma unroll
        for (int t = 0; t < 8; t++)
            #pragma unroll
            for (int k = 0; k < 4; k++) C2[g][t][k] = 0.0f;

    for (int kt = 0; kt < NTILES; kt++) {
        // ---- convert staged fp32 -> bf16 hi/lo tiles (smem -> smem) ----
        {
            const float4* Ks4 = (const float4*)(smc + STAGE_K);
            const float4* Vs4 = (const float4*)(smc + STAGE_V);
            #pragma unroll
            for (int it = 0; it < 8; it++) {
                int i = tid + it * NT;
                split_store(smc, OFF_KH, OFF_KL, i >> 4, i & 15, Ks4[i]);
            }
            #pragma unroll
            for (int it = 0; it < 8; it++) {
                int i = tid + it * NT;
                split_store(smc, OFF_VH, OFF_VL, i >> 4, i & 15, Vs4[i]);
            }
        }
        __syncthreads();   // bf16 tiles ready; staging fully consumed

        // ---- prefetch next tile into staging (hidden behind compute) ----
        if (kt + 1 < NTILES) {
            const float4* Kg4 = (const float4*)(Kb + (size_t)(kt + 1) * BLK * HDIM);
            const float4* Vg4 = (const float4*)(Vb + (size_t)(kt + 1) * BLK * HDIM);
            #pragma unroll
            for (int it = 0; it < 8; it++) {
                int i = tid + it * NT;
                cp16(sb + STAGE_K + i * 16, Kg4 + i);
                cp16(sb + STAGE_V + i * 16, Vg4 + i);
            }
        }
        CP_COMMIT();

        // ---- gemm1: C1 = Q K^T over warp's 32 rows x 64 cols ----
        float C1[2][8][4];
        #pragma unroll
        for (int g = 0; g < 2; g++)
            #pragma unroll
            for (int t = 0; t < 8; t++)
                #pragma unroll
                for (int k = 0; k < 4; k++) C1[g][t][k] = 0.0f;

        #pragma unroll
        for (int kc = 0; kc < 4; kc++) {
            uint32_t aH[2][4], aL[2][4];
            #pragma unroll
            for (int g = 0; g < 2; g++) {
                int arow = wq * 32 + g * 16 + aRowL;
                int ch = kc * 2 + aChunkOff;
                uint32_t ad = sb + OFF_QH + arow * 128 + ((ch ^ (arow & 7)) << 4);
                ldsm4(aH[g], ad);
                ldsm4(aL[g], ad + 16384);
            }
            #pragma unroll
            for (int nt2 = 0; nt2 < 4; nt2++) {
                int brow = wn * 64 + nt2 * 16 + bRowOff;
                int bch  = kc * 2 + bChunkOff;
                uint32_t bd = sb + OFF_KH + brow * 128 + ((bch ^ (brow & 7)) << 4);
                uint32_t bHf[4], bLf[4];
                ldsm4(bHf, bd);
                ldsm4(bLf, bd + 16384);
                #pragma unroll
                for (int g = 0; g < 2; g++) {
                    mma16816(C1[g][2 * nt2],     aH[g], bHf[0], bHf[1]);
                    mma16816(C1[g][2 * nt2],     aL[g], bHf[0], bHf[1]);
                    mma16816(C1[g][2 * nt2],     aH[g], bLf[0], bLf[1]);
                    mma16816(C1[g][2 * nt2 + 1], aH[g], bHf[2], bHf[3]);
                    mma16816(C1[g][2 * nt2 + 1], aL[g], bHf[2], bHf[3]);
                    mma16816(C1[g][2 * nt2 + 1], aH[g], bLf[2], bLf[3]);
                }
            }
        }

        // ---- fused epilogue + gemm2, one 16-k-col chunk at a time ----
        #pragma unroll
        for (int nt2 = 0; nt2 < 4; nt2++) {
            uint32_t ah[2][4], al[2][4];
            #pragma unroll
            for (int g = 0; g < 2; g++) {
                float* ag = attng
                    + (size_t)(wq * 32 + g * 16 + (lane >> 2)) * S_LEN
                    + (size_t)kt * BLK + wn * 64 + nt2 * 16 + (lane & 3) * 2;
                #pragma unroll
                for (int sub = 0; sub < 2; sub++) {
                    float* c = C1[g][2 * nt2 + sub];
                    float p0 = fmaxf(c[0] * 0.125f, 0.0f);
                    float p1 = fmaxf(c[1] * 0.125f, 0.0f);
                    float p2 = fmaxf(c[2] * 0.125f, 0.0f);
                    float p3 = fmaxf(c[3] * 0.125f, 0.0f);
                    __stcs((float2*)(ag + sub * 8),             make_float2(p0, p1));
                    __stcs((float2*)(ag + sub * 8 + 8 * S_LEN), make_float2(p2, p3));
                    uint32_t h01 = packbf(p0, p1);
                    uint32_t h23 = packbf(p2, p3);
                    float f0 = __uint_as_float(h01 << 16), f1 = __uint_as_float(h01 & 0xffff0000u);
                    float f2 = __uint_as_float(h23 << 16), f3 = __uint_as_float(h23 & 0xffff0000u);
                    ah[g][2 * sub]     = h01;
                    ah[g][2 * sub + 1] = h23;
                    al[g][2 * sub]     = packbf(p0 - f0, p1 - f1);
                    al[g][2 * sub + 1] = packbf(p2 - f2, p3 - f3);
                }
            }
            int vrow = wn * 64 + nt2 * 16 + vRowOff;
            #pragma unroll
            for (int ntV = 0; ntV < 4; ntV++) {
                int vch = ntV * 2 + vChunkOff;
                uint32_t vd = sb + OFF_VH + vrow * 128 + ((vch ^ (vrow & 7)) << 4);
                uint32_t bHf[4], bLf[4];
                ldsm4t(bHf, vd);
                ldsm4t(bLf, vd + 16384);
                #pragma unroll
                for (int g = 0; g < 2; g++) {
                    mma16816(C2[g][2 * ntV],     ah[g], bHf[0], bHf[1]);
                    mma16816(C2[g][2 * ntV],     al[g], bHf[0], bHf[1]);
                    mma16816(C2[g][2 * ntV],     ah[g], bLf[0], bLf[1]);
                    mma16816(C2[g][2 * ntV + 1], ah[g], bHf[2], bHf[3]);
                    mma16816(C2[g][2 * ntV + 1], al[g], bHf[2], bHf[3]);
                    mma16816(C2[g][2 * ntV + 1], ah[g], bLf[2], bLf[3]);
                }
            }
        }

        // staging must be full and bf16 tiles free before next convert
        CP_WAIT0();
        __syncthreads();
    }

    // ---- split-k reduction of C2 across wn pairs, then write ctx ----
    float* red = (float*)smc;        // overlays bf16 tiles (done with them)
    if (wn == 1) {
        #pragma unroll
        for (int g = 0; g < 2; g++) {
            int r = wq * 32 + g * 16 + (lane >> 2);
            #pragma unroll
            for (int t = 0; t < 8; t++) {
                int col = (t >> 1) * 16 + (t & 1) * 8 + (lane & 3) * 2;
                *(float2*)&red[(size_t)r * RED_STRIDE + col] =
                    make_float2(C2[g][t][0], C2[g][t][1]);
                *(float2*)&red[(size_t)(r + 8) * RED_STRIDE + col] =
                    make_float2(C2[g][t][2], C2[g][t][3]);
            }
        }
    }
    __syncthreads();
    if (wn == 0) {
        #pragma unroll
        for (int g = 0; g < 2; g++) {
            int r = wq * 32 + g * 16 + (lane >> 2);
            #pragma unroll
            for (int t = 0; t < 8; t++) {
                int col = (t >> 1) * 16 + (t & 1) * 8 + (lane & 3) * 2;
                float2 p0 = *(float2*)&red[(size_t)r * RED_STRIDE + col];
                float2 p1 = *(float2*)&red[(size_t)(r + 8) * RED_STRIDE + col];
                *(float2*)&ctxg[(size_t)r * HDIM + col] =
                    make_float2(C2[g][t][0] + p0.x, C2[g][t][1] + p0.y);
                *(float2*)&ctxg[(size_t)(r + 8) * HDIM + col] =
                    make_float2(C2[g][t][2] + p1.x, C2[g][t][3] + p1.y);
            }
        }
    }
}

extern "C" void kernel_launch(void* const* d_in, const int* in_sizes, int n_in,
                              void* d_out, int out_size) {
    const float* Q = (const float*)d_in[0];
    const float* K = (const float*)d_in[1];
    const float* V = (const float*)d_in[2];
    float* ctx  = (float*)d_out;
    float* attn = (float*)d_out + CTX_ELEMS;

    cudaFuncSetAttribute(relu_attn_mma3_kernel,
                         cudaFuncAttributeMaxDynamicSharedMemorySize, SMEM_BYTES);
    dim3 grid(S_LEN / BLK, 64);
    relu_attn_mma3_kernel<<<grid, NT, SMEM_BYTES>>>(Q, K, V, ctx, attn);
}